// round 3
// baseline (speedup 1.0000x reference)
#include <cuda_runtime.h>
#include <math.h>

// Allpass biquad over [B, 1, T] fp32, T = 480000.
// Key fact: poles decay at 0.414/sample -> M^32 == 0 in fp32. So:
//  - the inter-lane scan is a 4-tap stencil (depth-1 shuffles), not a log-scan
//  - the tile carry is exact: si_next = W[lane31]  (M^256 == 0)
//  - the chunk warm-up is a 32-sample dot product with impulse-response
//    weights, reduced with a 5-step butterfly (no serial recurrence)

#define FULL 0xffffffffu
#define R 8                   // samples per lane
#define TILE 256              // 32 lanes * R
#define CHUNK_TILES 5         // 1280 samples per warp-chunk
#define CHUNK (CHUNK_TILES * TILE)
#define T_LEN 480000
#define WARMUP 32

struct KParams {
    float b0, b1, b2, a1, a2;
    float S1[4], S2[4], S3[4];   // M^8, M^16, M^24 (row-major 2x2)
    float c0[R], c1[R];          // row 0 of M^(k+1), k=0..R-1
    float Q[32][4];              // M^(8*lane) (underflows to 0 for lane>=5)
    float h0[32], h1[32];        // warm-up weights: s_in = sum h*x
};

__global__ void __launch_bounds__(256)
allpass_biquad_kernel(const float* __restrict__ x, float* __restrict__ y,
                      const KParams p, int chunks_per_row, int total_chunks)
{
    const int warp_id = (blockIdx.x * blockDim.x + threadIdx.x) >> 5;
    const int lane = threadIdx.x & 31;
    if (warp_id >= total_chunks) return;

    const int row   = warp_id / chunks_per_row;
    const int chunk = warp_id % chunks_per_row;
    const float* xr = x + (size_t)row * T_LEN;
    float*       yr = y + (size_t)row * T_LEN;
    const int start = chunk * CHUNK;

    const float b0 = p.b0, b1 = p.b1, b2 = p.b2, a1 = p.a1, a2 = p.a2;
    const float q00 = p.Q[lane][0], q01 = p.Q[lane][1];
    const float q10 = p.Q[lane][2], q11 = p.Q[lane][3];

    // ---- warm-up: dot product with impulse-response weights ----
    float si0 = 0.0f, si1 = 0.0f;   // incoming y-state (y_{-1}, y_{-2})
    float cx1 = 0.0f, cx2 = 0.0f;   // x_{-1}, x_{-2}
    if (chunk != 0) {
        const float xw = xr[start - WARMUP + lane];  // one coalesced line
        float g0 = p.h0[lane] * xw;
        float g1 = p.h1[lane] * xw;
        #pragma unroll
        for (int s = 16; s >= 1; s >>= 1) {
            g0 += __shfl_xor_sync(FULL, g0, s);
            g1 += __shfl_xor_sync(FULL, g1, s);
        }
        si0 = g0; si1 = g1;
        cx1 = __shfl_sync(FULL, xw, 31);
        cx2 = __shfl_sync(FULL, xw, 30);
    }

    #pragma unroll
    for (int t = 0; t < CHUNK_TILES; t++) {
        const int goff = start + t * TILE + lane * R;

        const float4* px = reinterpret_cast<const float4*>(xr + goff);
        const float4 xa = __ldcs(px + 0);
        const float4 xb = __ldcs(px + 1);
        const float xs[R] = {xa.x, xa.y, xa.z, xa.w, xb.x, xb.y, xb.z, xb.w};

        // x history from neighbor lane (lane 0 uses carry)
        float xm1 = __shfl_up_sync(FULL, xs[7], 1);
        float xm2 = __shfl_up_sync(FULL, xs[6], 1);
        if (lane == 0) { xm1 = cx1; xm2 = cx2; }

        // particular solution with zero incoming y-state
        float yp[R];
        {
            float py1 = 0.0f, py2 = 0.0f, xp1 = xm1, xp2 = xm2;
            #pragma unroll
            for (int k = 0; k < R; k++) {
                const float fir = b0 * xs[k] + b1 * xp1 + b2 * xp2;
                const float yn  = fir - a1 * py1 - a2 * py2;
                yp[k] = yn;
                py2 = py1; py1 = yn;
                xp2 = xp1; xp1 = xs[k];
            }
        }
        const float F0 = yp[R - 1];
        const float F1 = yp[R - 2];

        // 4-tap stencil (M^32 == 0): W = F + S1*F(-1) + S2*F(-2) + S3*F(-3)
        // the three shuffle-ups are independent -> depth 1
        float a0m = __shfl_up_sync(FULL, F0, 1);
        float a1m = __shfl_up_sync(FULL, F1, 1);
        float b0m = __shfl_up_sync(FULL, F0, 2);
        float b1m = __shfl_up_sync(FULL, F1, 2);
        float c0m = __shfl_up_sync(FULL, F0, 3);
        float c1m = __shfl_up_sync(FULL, F1, 3);
        if (lane < 1) { a0m = 0.0f; a1m = 0.0f; }
        if (lane < 2) { b0m = 0.0f; b1m = 0.0f; }
        if (lane < 3) { c0m = 0.0f; c1m = 0.0f; }
        const float W0 = F0 + p.S1[0] * a0m + p.S1[1] * a1m
                            + p.S2[0] * b0m + p.S2[1] * b1m
                            + p.S3[0] * c0m + p.S3[1] * c1m;
        const float W1 = F1 + p.S1[2] * a0m + p.S1[3] * a1m
                            + p.S2[2] * b0m + p.S2[3] * b1m
                            + p.S3[2] * c0m + p.S3[3] * c1m;

        // incoming state for this lane: sigma = W_{lane-1} + M^(8*lane) * si
        float vp0 = __shfl_up_sync(FULL, W0, 1);
        float vp1 = __shfl_up_sync(FULL, W1, 1);
        if (lane == 0) { vp0 = 0.0f; vp1 = 0.0f; }
        const float sg0 = vp0 + q00 * si0 + q01 * si1;
        const float sg1 = vp1 + q10 * si0 + q11 * si1;

        // correct and store (streaming)
        float4 o0, o1;
        o0.x = yp[0] + p.c0[0] * sg0 + p.c1[0] * sg1;
        o0.y = yp[1] + p.c0[1] * sg0 + p.c1[1] * sg1;
        o0.z = yp[2] + p.c0[2] * sg0 + p.c1[2] * sg1;
        o0.w = yp[3] + p.c0[3] * sg0 + p.c1[3] * sg1;
        o1.x = yp[4] + p.c0[4] * sg0 + p.c1[4] * sg1;
        o1.y = yp[5] + p.c0[5] * sg0 + p.c1[5] * sg1;
        o1.z = yp[6] + p.c0[6] * sg0 + p.c1[6] * sg1;
        o1.w = yp[7] + p.c0[7] * sg0 + p.c1[7] * sg1;
        float4* py4 = reinterpret_cast<float4*>(yr + goff);
        __stcs(py4 + 0, o0);
        __stcs(py4 + 1, o1);

        // carries to next tile (exact: M^256 == 0 in fp32)
        si0 = __shfl_sync(FULL, W0, 31);
        si1 = __shfl_sync(FULL, W1, 31);
        cx1 = __shfl_sync(FULL, xs[7], 31);
        cx2 = __shfl_sync(FULL, xs[6], 31);
    }
}

// host-side 2x2 (double precision) helpers
struct M2d { double a, b, c, d; };
static inline M2d mmul_h(const M2d& x, const M2d& y) {
    return { x.a * y.a + x.b * y.c, x.a * y.b + x.b * y.d,
             x.c * y.a + x.d * y.c, x.c * y.b + x.d * y.d };
}

extern "C" void kernel_launch(void* const* d_in, const int* in_sizes, int n_in,
                              void* d_out, int out_size)
{
    const float* x = (const float*)d_in[0];
    float* y = (float*)d_out;

    const int total = in_sizes[0];
    const int B = total / T_LEN;   // 64

    // Coefficients in float64 then cast, matching the numpy reference.
    const double w0    = 2.0 * M_PI * 4000.0 / 16000.0;
    const double alpha = sin(w0) / (2.0 * 0.707);
    const double cw0   = cos(w0);
    const double a0d   = 1.0 + alpha;
    KParams p;
    p.b0 = (float)((1.0 - alpha) / a0d);
    p.b1 = (float)((-2.0 * cw0) / a0d);
    p.b2 = (float)((1.0 + alpha) / a0d);
    p.a1 = (float)((-2.0 * cw0) / a0d);
    p.a2 = (float)((1.0 - alpha) / a0d);

    // transition matrix M = [[-a1, -a2], [1, 0]] with float-cast coeffs
    M2d M = { -(double)p.a1, -(double)p.a2, 1.0, 0.0 };

    // c0/c1: row 0 of M^(k+1), k = 0..R-1
    {
        M2d cur = M;
        p.c0[0] = (float)cur.a; p.c1[0] = (float)cur.b;
        for (int k = 1; k < R; k++) {
            cur = mmul_h(cur, M);
            p.c0[k] = (float)cur.a; p.c1[k] = (float)cur.b;
        }
    }
    // S1 = M^8, S2 = M^16, S3 = M^24; Q[lane] = M^(8*lane)
    {
        M2d m8 = M;
        for (int j = 1; j < R; j++) m8 = mmul_h(m8, M);
        M2d m16 = mmul_h(m8, m8);
        M2d m24 = mmul_h(m16, m8);
        p.S1[0] = (float)m8.a;  p.S1[1] = (float)m8.b;
        p.S1[2] = (float)m8.c;  p.S1[3] = (float)m8.d;
        p.S2[0] = (float)m16.a; p.S2[1] = (float)m16.b;
        p.S2[2] = (float)m16.c; p.S2[3] = (float)m16.d;
        p.S3[0] = (float)m24.a; p.S3[1] = (float)m24.b;
        p.S3[2] = (float)m24.c; p.S3[3] = (float)m24.d;

        M2d q = { 1.0, 0.0, 0.0, 1.0 };
        for (int lane = 0; lane < 32; lane++) {
            p.Q[lane][0] = (float)q.a; p.Q[lane][1] = (float)q.b;
            p.Q[lane][2] = (float)q.c; p.Q[lane][3] = (float)q.d;
            q = mmul_h(m8, q);
        }
    }
    // warm-up weights: impulse response over 32 steps.
    // imp[n] = response at step n to unit impulse at step 0.
    // s_in = (y_{-1}, y_{-2}) after filtering x[start-32 .. start-1] from zero
    // state: h0[k] = imp[31-k], h1[k] = imp[30-k] (imp[-1] = 0).
    {
        double imp[WARMUP];
        double py1 = 0.0, py2 = 0.0, xp1 = 0.0, xp2 = 0.0;
        for (int n = 0; n < WARMUP; n++) {
            double xk = (n == 0) ? 1.0 : 0.0;
            double yn = (double)p.b0 * xk + (double)p.b1 * xp1
                      + (double)p.b2 * xp2
                      - (double)p.a1 * py1 - (double)p.a2 * py2;
            imp[n] = yn;
            py2 = py1; py1 = yn;
            xp2 = xp1; xp1 = xk;
        }
        for (int k = 0; k < WARMUP; k++) {
            p.h0[k] = (float)imp[31 - k];
            p.h1[k] = (31 - k - 1 >= 0) ? (float)imp[31 - k - 1] : 0.0f;
        }
    }

    const int chunks_per_row = T_LEN / CHUNK;        // 375
    const int total_chunks   = B * chunks_per_row;   // 24000 warps
    const int threads = 256;
    const int blocks  = (total_chunks * 32 + threads - 1) / threads;

    allpass_biquad_kernel<<<blocks, threads>>>(x, y, p, chunks_per_row,
                                               total_chunks);
}

// round 4
// speedup vs baseline: 1.4210x; 1.4210x over previous
#include <cuda_runtime.h>
#include <math.h>

// Allpass biquad over [B, 1, T] fp32, T = 480000.
// Thread-serial design: each thread owns an independent contiguous 64-sample
// segment (poles decay 0.414/sample -> a 16-sample warm-up reconstructs state
// to ~7.5e-7). Global traffic is fully coalesced via a padded-transpose
// shared-memory staging buffer. No warp shuffles, no inter-lane dependencies.

#define T_LEN    480000
#define SEG      64                 // samples per thread
#define NTHREADS 256
#define CHUNK    (SEG * NTHREADS)   // 16384 samples per block
#define CHUNKS_PER_ROW 30           // 29 full + tail of 4864 (= 76 segments)
#define WARM     16
#define PAD      257                // 256 columns + 1 pad float
#define SMEM_FLOATS (SEG * PAD)     // 16448 floats = 65792 bytes

__global__ void __launch_bounds__(NTHREADS, 3)
allpass_kernel(const float* __restrict__ x, float* __restrict__ y,
               float b0, float b1, float b2, float a1, float a2)
{
    extern __shared__ float sm[];   // logical [SEG][PAD], sm[k*PAD + i]
    const int tid   = threadIdx.x;
    const int chunk = blockIdx.x;
    const int row   = blockIdx.y;

    const float* xr = x + (size_t)row * T_LEN;
    float*       yr = y + (size_t)row * T_LEN;
    const int base      = chunk * CHUNK;
    const int chunk_len = min(CHUNK, T_LEN - base);   // 16384 or 4864
    const int n_seg     = chunk_len >> 6;             // 256 or 76

    // ---- stage-in: coalesced LDG.128, transposed STS (2-way conflict) ----
    #pragma unroll
    for (int r = 0; r < 16; r++) {
        const int j = (r * NTHREADS + tid) * 4;
        if (j < chunk_len) {
            const float4 v = __ldcs(reinterpret_cast<const float4*>(xr + base + j));
            const int i = j >> 6;
            const int k = j & 63;
            float* d = &sm[k * PAD + i];
            d[0 * PAD] = v.x;
            d[1 * PAD] = v.y;
            d[2 * PAD] = v.z;
            d[3 * PAD] = v.w;
        }
    }
    __syncthreads();

    // ---- warm-up: 16 serial samples establish (y1,y2,x1,x2) ----
    const int i = tid;
    float y1 = 0.0f, y2 = 0.0f, x1 = 0.0f, x2 = 0.0f;
    if (i < n_seg) {
        if (i > 0) {
            // tail of the previous segment, already staged in smem
            #pragma unroll
            for (int k = 0; k < WARM; k++) {
                const float xv = sm[(SEG - WARM + k) * PAD + (i - 1)];
                const float yn = b0 * xv + b1 * x1 + b2 * x2
                               - a1 * y1 - a2 * y2;
                y2 = y1; y1 = yn; x2 = x1; x1 = xv;
            }
        } else if (chunk > 0) {
            // thread 0: previous chunk's tail, straight from global
            #pragma unroll
            for (int k = 0; k < WARM; k++) {
                const float xv = __ldg(xr + base - WARM + k);
                const float yn = b0 * xv + b1 * x1 + b2 * x2
                               - a1 * y1 - a2 * y2;
                y2 = y1; y1 = yn; x2 = x1; x1 = xv;
            }
        }
        // chunk == 0, i == 0: true zero initial state
    }
    __syncthreads();   // warm-up reads must finish before in-place overwrite

    // ---- recurrence: 64 samples, conflict-free LDS/STS, in-place ----
    if (i < n_seg) {
        #pragma unroll
        for (int k = 0; k < SEG; k++) {
            const float xv = sm[k * PAD + i];
            const float yn = b0 * xv + b1 * x1 + b2 * x2
                           - a1 * y1 - a2 * y2;
            sm[k * PAD + i] = yn;
            x2 = x1; x1 = xv; y2 = y1; y1 = yn;
        }
    }
    __syncthreads();

    // ---- gather-out: transposed LDS (2-way conflict), coalesced STG.128 ----
    #pragma unroll
    for (int r = 0; r < 16; r++) {
        const int j = (r * NTHREADS + tid) * 4;
        if (j < chunk_len) {
            const int ii = j >> 6;
            const int k  = j & 63;
            const float* s = &sm[k * PAD + ii];
            const float4 v = make_float4(s[0 * PAD], s[1 * PAD],
                                         s[2 * PAD], s[3 * PAD]);
            __stcs(reinterpret_cast<float4*>(yr + base + j), v);
        }
    }
}

extern "C" void kernel_launch(void* const* d_in, const int* in_sizes, int n_in,
                              void* d_out, int out_size)
{
    const float* x = (const float*)d_in[0];
    float* y = (float*)d_out;

    const int total = in_sizes[0];
    const int B = total / T_LEN;   // 64

    // Coefficients in float64 then cast, matching the numpy reference.
    const double w0    = 2.0 * M_PI * 4000.0 / 16000.0;
    const double alpha = sin(w0) / (2.0 * 0.707);
    const double cw0   = cos(w0);
    const double a0d   = 1.0 + alpha;
    const float b0 = (float)((1.0 - alpha) / a0d);
    const float b1 = (float)((-2.0 * cw0) / a0d);
    const float b2 = (float)((1.0 + alpha) / a0d);
    const float a1 = (float)((-2.0 * cw0) / a0d);
    const float a2 = (float)((1.0 - alpha) / a0d);

    static bool attr_set = false;
    if (!attr_set) {
        cudaFuncSetAttribute(allpass_kernel,
                             cudaFuncAttributeMaxDynamicSharedMemorySize,
                             SMEM_FLOATS * (int)sizeof(float));
        attr_set = true;
    }

    dim3 grid(CHUNKS_PER_ROW, B);
    allpass_kernel<<<grid, NTHREADS, SMEM_FLOATS * sizeof(float)>>>(
        x, y, b0, b1, b2, a1, a2);
}